// round 15
// baseline (speedup 1.0000x reference)
#include <cuda_runtime.h>
#include <cuda_bf16.h>
#include <cstdint>

// out[b, a*16+c, d, l] = sum_k s[b,(c-a)%16,l,k] * t[b,c,l,d-k]  (linear conv)
// Per (b,c,l): D[128d x 16m] = A[128x64] * B[16x64]^T,
//   A[d][k] = t_pad[d-k] (Toeplitz), B[m][k] = s[b,m,l,k].
// mma.sync.m16n8k16 bf16, 3-term truncation split (hi*hi + hi*lo + lo*hi).
// R15: pair-table A (R14) + XOR-swizzled 128B B rows (saves 4KB, conflict-free
// both directions) => single-pass R13 staging fits at 3 CTAs/SM. 4 barriers/c.

typedef unsigned int u32;

#define OFF_B    0
#define B_SIDE   2048          // 16 rows * 128B, chunk ^= (m&7) swizzle
#define B_PERL   4096          // x8 l = 32768
#define OFF_P    32768         // pair table: 8 l * 2 sides * 96 * 4B = 6144
#define OFF_STG  38912         // staging: 8 m * 1156 floats = 36992B
#define STG_MS   1156          // staging m-stride (floats)
#define SMEM_TOTAL 75904
#define SRS      516           // s_raw m-stride (floats), 16B-aligned rows

__device__ __forceinline__ u32 pack_bf2(float lo, float hi) {   // {lo16, hi16}
    u32 r;
    asm("cvt.rn.satfinite.bf16x2.f32 %0, %1, %2;" : "=r"(r) : "f"(hi), "f"(lo));
    return r;
}
__device__ __forceinline__ void mma_bf16(float* c, const u32* a, u32 b0, u32 b1) {
    asm("mma.sync.aligned.m16n8k16.row.col.f32.bf16.bf16.f32 "
        "{%0,%1,%2,%3}, {%4,%5,%6,%7}, {%8,%9}, {%0,%1,%2,%3};"
        : "+f"(c[0]), "+f"(c[1]), "+f"(c[2]), "+f"(c[3])
        : "r"(a[0]), "r"(a[1]), "r"(a[2]), "r"(a[3]), "r"(b0), "r"(b1));
}

// warp-local pair-table build for l = w: P[e] = {t_pad[y], t_pad[y-1]}, y=e-14
__device__ __forceinline__ void build_P(char* smem, const float* __restrict__ tg,
                                        int w, int lane) {
    u32* ph = (u32*)(smem + OFF_P) + w * 192;
    #pragma unroll
    for (int j = 0; j < 3; j++) {
        int e = lane + 32 * j;              // 0..95
        int y = e - 14;
        float x0 = ((unsigned)y < 63u) ? __ldg(tg + y) : 0.0f;
        float x1 = ((unsigned)(y - 1) < 63u) ? __ldg(tg + y - 1) : 0.0f;
        u32 u0 = __float_as_uint(x0), u1 = __float_as_uint(x1);
        u32 hw = __byte_perm(u0, u1, 0x7632);          // {hi16(x0), hi16(x1)}
        float h0 = __uint_as_float(u0 & 0xFFFF0000u);
        float h1 = __uint_as_float(u1 & 0xFFFF0000u);
        ph[e]      = hw;
        ph[96 + e] = pack_bf2(x0 - h0, x1 - h1);
    }
}

__global__ __launch_bounds__(256, 3)
void conv_mma(const float* __restrict__ s_g,
              const float* __restrict__ t_g,
              float* __restrict__ out) {
    extern __shared__ char smem[];
    float* stgf = (float*)(smem + OFF_STG);
    const int tid = threadIdx.x, wid = tid >> 5, lane = tid & 31;
    const int gid = lane >> 2, tig = lane & 3;
    const int lq = blockIdx.x, b = blockIdx.y, cg = blockIdx.z;
    const int lbase = lq * 8;
    const float* tbase = t_g + (((size_t)b * 16 + cg * 2) * 64 + lbase + wid) * 63;

    // ---- prologue: stage s tile coalesced (overlays staging region) ----
    float* s_raw = stgf;                      // 16 m * 516 floats = 33024B
    {
        const float* sgb = s_g + ((size_t)b * 1024 + lbase) * 63;   // 16B-aligned
        for (int i = tid; i < 2016; i += 256) {                     // 16 m * 126 f4
            int m = i / 126, j = i - m * 126;
            float4 v = *(const float4*)(sgb + (size_t)m * 4032 + j * 4);
            *(float4*)(s_raw + m * SRS + j * 4) = v;
        }
    }
    __syncthreads();

    // ---- warp-local B build: warp w -> l = w; lane = (m, h); XOR swizzle ----
    {
        int m = lane >> 1, h = lane & 1;
        const float* sp = s_raw + m * SRS + wid * 63 + h * 32;
        u32 hw[16], lw[16];
        #pragma unroll
        for (int q = 0; q < 16; q++) {
            float x0 = sp[2 * q];                    // k = h*32+2q <= 62
            float x1 = 0.0f;
            if (h * 32 + 2 * q + 1 < 63) x1 = sp[2 * q + 1];
            u32 u0 = __float_as_uint(x0), u1 = __float_as_uint(x1);
            hw[q] = __byte_perm(u0, u1, 0x7632);
            float h0 = __uint_as_float(u0 & 0xFFFF0000u);
            float h1 = __uint_as_float(u1 & 0xFFFF0000u);
            lw[q] = pack_bf2(x0 - h0, x1 - h1);
        }
        char* bh = smem + OFF_B + wid * B_PERL + m * 128;
        char* bl = bh + B_SIDE;
        #pragma unroll
        for (int cc = 0; cc < 4; cc++) {
            int g = ((h * 4 + cc) ^ (m & 7)) * 16;   // swizzled chunk offset
            *(uint4*)(bh + g) =
                make_uint4(hw[cc*4], hw[cc*4+1], hw[cc*4+2], hw[cc*4+3]);
            *(uint4*)(bl + g) =
                make_uint4(lw[cc*4], lw[cc*4+1], lw[cc*4+2], lw[cc*4+3]);
        }
    }
    // pair table for first c (warp-private write/read: no barrier needed)
    build_P(smem, tbase, wid, lane);
    __syncthreads();   // B ready; s_raw consumed -> staging free

    const int l_off = lane & 7, qq = lane >> 3;
    const char* bb = smem + OFF_B + wid * B_PERL;
    const u32* ph = (const u32*)(smem + OFF_P) + wid * 192 + (gid - 2 * tig + 6);
    const u32* pl = ph + 96;

    #pragma unroll 1
    for (int ci = 0; ci < 2; ci++) {
        const int c = cg * 2 + ci;

        #pragma unroll 1
        for (int p = 0; p < 2; p++) {          // p doubles as nt
            // ---- mainloop half: n-tile nt = p for this warp's l ----
            float acc[8][4];
            u32 bfr[4][2][2];   // [kt][side][b0/b1]
            #pragma unroll
            for (int kt = 0; kt < 4; kt++)
                #pragma unroll
                for (int sd = 0; sd < 2; sd++) {
                    const char* rw = bb + sd * B_SIDE + (8 * p + gid) * 128
                                   + tig * 4;
                    bfr[kt][sd][0] = *(const u32*)(rw + (((2*kt)   ^ gid) * 16));
                    bfr[kt][sd][1] = *(const u32*)(rw + (((2*kt+1) ^ gid) * 16));
                }
            #pragma unroll
            for (int md = 0; md < 8; md++)
                #pragma unroll
                for (int e = 0; e < 4; e++) acc[md][e] = 0.0f;

            #pragma unroll
            for (int sg = 0; sg < 5; sg++) {               // sigma = md - kt
                u32 Pm = ph[16 * sg], P0 = ph[16 * sg + 8], Pp = ph[16 * sg + 16];
                u32 ah4[4] = { P0, Pp, Pm, P0 };           // a3 == a0 (Toeplitz)
                u32 Qm = pl[16 * sg], Q0 = pl[16 * sg + 8], Qp = pl[16 * sg + 16];
                u32 al4[4] = { Q0, Qp, Qm, Q0 };
                #pragma unroll
                for (int kt = 0; kt < 4; kt++) {
                    const int md = sg + kt;                // 0..7
                    mma_bf16(acc[md], ah4, bfr[kt][0][0], bfr[kt][0][1]); // hi*hi
                    mma_bf16(acc[md], ah4, bfr[kt][1][0], bfr[kt][1][1]); // hi*lo
                    mma_bf16(acc[md], al4, bfr[kt][0][0], bfr[kt][0][1]); // lo*hi
                }
            }

            // ---- hoisted pair-table build for c+1 (warp-private) ----
            if (p == 1 && ci < 1)
                build_P(smem, tbase + (size_t)64 * 63, wid, lane);

            __syncthreads();   // staging writable (prev store readers done)

            // ---- stage this half's 8 m across all 128 d ----
            #pragma unroll
            for (int md = 0; md < 8; md++) {
                int d0 = 16 * md + gid;
                float* st = stgf + (2 * tig) * STG_MS + d0 * 9 + wid;
                st[0]            = acc[md][0];
                st[STG_MS]       = acc[md][1];
                st[72]           = acc[md][2];
                st[STG_MS + 72]  = acc[md][3];
            }
            __syncthreads();

            // ---- store (streamed) ----
            int m = 8 * p + wid;
            int a = (c - m) & 15;
            float* ob = out + ((size_t)(b * 256 + a * 16 + c) << 13)
                      + (size_t)(8 * qq) * 64 + lbase + l_off;
            const float* sm_m = stgf + wid * STG_MS + 72 * qq + l_off;
            #pragma unroll
            for (int jj = 0; jj < 32; jj++) {
                int dlo = jj & 7, dhi = jj >> 3;
                __stcs(ob + (size_t)(dlo + 32 * dhi) * 64,
                       sm_m[9 * dlo + 288 * dhi]);
            }
            // no trailing barrier: next mma half touches only warp-private
            // B/P reads; the next pre-stage barrier protects staging.
        }
    }
}

extern "C" void kernel_launch(void* const* d_in, const int* in_sizes, int n_in,
                              void* d_out, int out_size) {
    const float* s = (const float*)d_in[0];
    const float* t = (const float*)d_in[1];
    float* out = (float*)d_out;

    cudaFuncSetAttribute(conv_mma,
                         cudaFuncAttributeMaxDynamicSharedMemorySize, SMEM_TOTAL);

    dim3 grid(8, 32, 8);   // (l-oct, b, c-pair) = 2048 blocks, 2 c's each
    conv_mma<<<grid, 256, SMEM_TOTAL>>>(s, t, out);
}

// round 16
// speedup vs baseline: 1.4593x; 1.4593x over previous
#include <cuda_runtime.h>
#include <cuda_bf16.h>
#include <cstdint>

// out[b, a*16+c, d, l] = sum_k s[b,(c-a)%16,l,k] * t[b,c,l,d-k]  (linear conv)
// Per (b,c,l): D[128d x 16m] = A[128x64] * B[16x64]^T,
//   A[d][k] = t_pad[d-k] (Toeplitz), B[m][k] = s[b,m,l,k].
// mma.sync.m16n8k16 bf16, 3-term truncation split (hi*hi + hi*lo + lo*hi).
// R16 = R13 frame (2 CTAs/SM, NO reg cap -- the R14/R15 occupancy push caused
// spills) + pair-table A: Toeplitz A collapsed to P[e]={t[y],t[y-1]} per
// (l,side); A-frags {P0,Pp,Pm,P0} via broadcast LDS. A smem 40KB->6KB,
// A-build 48 LDG+12 STS.128 -> 6 LDG+6 STS per warp per c.

typedef unsigned int u32;

#define OFF_B    0
#define B_SIDE   2304          // 16 rows * 144B
#define B_PERL   4608          // x8 l = 36864
#define OFF_P    36864         // pair table: 8 l * 2 sides * 96 * 4B = 6144
#define OFF_STG  43008         // staging: 8 m * 1156 floats = 36992B
#define STG_MS   1156          // staging m-stride (floats)
#define SMEM_TOTAL 80000
#define SRS      516           // s_raw m-stride (floats), 16B-aligned rows

__device__ __forceinline__ u32 pack_bf2(float lo, float hi) {   // {lo16, hi16}
    u32 r;
    asm("cvt.rn.satfinite.bf16x2.f32 %0, %1, %2;" : "=r"(r) : "f"(hi), "f"(lo));
    return r;
}
__device__ __forceinline__ void mma_bf16(float* c, const u32* a, u32 b0, u32 b1) {
    asm("mma.sync.aligned.m16n8k16.row.col.f32.bf16.bf16.f32 "
        "{%0,%1,%2,%3}, {%4,%5,%6,%7}, {%8,%9}, {%0,%1,%2,%3};"
        : "+f"(c[0]), "+f"(c[1]), "+f"(c[2]), "+f"(c[3])
        : "r"(a[0]), "r"(a[1]), "r"(a[2]), "r"(a[3]), "r"(b0), "r"(b1));
}

// warp-local pair-table build for l = w: P[e] = {t_pad[y], t_pad[y-1]}, y=e-14
__device__ __forceinline__ void build_P(char* smem, const float* __restrict__ tg,
                                        int w, int lane) {
    u32* ph = (u32*)(smem + OFF_P) + w * 192;
    #pragma unroll
    for (int j = 0; j < 3; j++) {
        int e = lane + 32 * j;              // 0..95
        int y = e - 14;
        float x0 = ((unsigned)y < 63u) ? __ldg(tg + y) : 0.0f;
        float x1 = ((unsigned)(y - 1) < 63u) ? __ldg(tg + y - 1) : 0.0f;
        u32 u0 = __float_as_uint(x0), u1 = __float_as_uint(x1);
        u32 hw = __byte_perm(u0, u1, 0x7632);          // {hi16(x0), hi16(x1)}
        float h0 = __uint_as_float(u0 & 0xFFFF0000u);
        float h1 = __uint_as_float(u1 & 0xFFFF0000u);
        ph[e]      = hw;
        ph[96 + e] = pack_bf2(x0 - h0, x1 - h1);
    }
}

__global__ __launch_bounds__(256, 2)
void conv_mma(const float* __restrict__ s_g,
              const float* __restrict__ t_g,
              float* __restrict__ out) {
    extern __shared__ char smem[];
    float* stgf = (float*)(smem + OFF_STG);
    const int tid = threadIdx.x, wid = tid >> 5, lane = tid & 31;
    const int gid = lane >> 2, tig = lane & 3;
    const int lq = blockIdx.x, b = blockIdx.y, cg = blockIdx.z;
    const int lbase = lq * 8;
    const float* tbase = t_g + (((size_t)b * 16 + cg * 2) * 64 + lbase + wid) * 63;

    // ---- prologue: stage s tile coalesced (overlays staging region) ----
    float* s_raw = stgf;                      // 16 m * 516 floats = 33024B
    {
        const float* sgb = s_g + ((size_t)b * 1024 + lbase) * 63;   // 16B-aligned
        for (int i = tid; i < 2016; i += 256) {                     // 16 m * 126 f4
            int m = i / 126, j = i - m * 126;
            float4 v = *(const float4*)(sgb + (size_t)m * 4032 + j * 4);
            *(float4*)(s_raw + m * SRS + j * 4) = v;
        }
    }
    __syncthreads();

    // ---- warp-local B build: warp w -> l = w; lane = (m, h) ----
    {
        int m = lane >> 1, h = lane & 1;
        const float* sp = s_raw + m * SRS + wid * 63 + h * 32;
        u32 hw[16], lw[16];
        #pragma unroll
        for (int q = 0; q < 16; q++) {
            float x0 = sp[2 * q];                    // k = h*32+2q <= 62
            float x1 = 0.0f;
            if (h * 32 + 2 * q + 1 < 63) x1 = sp[2 * q + 1];
            u32 u0 = __float_as_uint(x0), u1 = __float_as_uint(x1);
            hw[q] = __byte_perm(u0, u1, 0x7632);
            float h0 = __uint_as_float(u0 & 0xFFFF0000u);
            float h1 = __uint_as_float(u1 & 0xFFFF0000u);
            lw[q] = pack_bf2(x0 - h0, x1 - h1);
        }
        char* bh = smem + OFF_B + wid * B_PERL + m * 144 + h * 64;
        char* bl = bh + B_SIDE;
        #pragma unroll
        for (int cc = 0; cc < 4; cc++) {
            *(uint4*)(bh + cc * 16) =
                make_uint4(hw[cc*4], hw[cc*4+1], hw[cc*4+2], hw[cc*4+3]);
            *(uint4*)(bl + cc * 16) =
                make_uint4(lw[cc*4], lw[cc*4+1], lw[cc*4+2], lw[cc*4+3]);
        }
    }
    // pair table for first c (warp-private write/read: no barrier needed)
    build_P(smem, tbase, wid, lane);
    __syncthreads();   // B ready; s_raw consumed -> staging free

    const int l_off = lane & 7, qq = lane >> 3;
    const char* bb = smem + OFF_B + wid * B_PERL;
    const u32* ph = (const u32*)(smem + OFF_P) + wid * 192 + (gid - 2 * tig + 6);
    const u32* pl = ph + 96;

    #pragma unroll 1
    for (int ci = 0; ci < 2; ci++) {
        const int c = cg * 2 + ci;

        #pragma unroll 1
        for (int p = 0; p < 2; p++) {          // p doubles as nt
            // ---- mainloop half: n-tile nt = p for this warp's l ----
            float acc[8][4];
            u32 bfr[4][2][2];   // [kt][side][b0/b1]
            #pragma unroll
            for (int kt = 0; kt < 4; kt++)
                #pragma unroll
                for (int sd = 0; sd < 2; sd++) {
                    const char* ad = bb + sd * B_SIDE + (8 * p + gid) * 144
                                   + kt * 32 + tig * 4;
                    bfr[kt][sd][0] = *(const u32*)ad;
                    bfr[kt][sd][1] = *(const u32*)(ad + 16);
                }
            #pragma unroll
            for (int md = 0; md < 8; md++)
                #pragma unroll
                for (int e = 0; e < 4; e++) acc[md][e] = 0.0f;

            #pragma unroll
            for (int sg = 0; sg < 5; sg++) {               // sigma = md - kt
                u32 Pm = ph[16 * sg], P0 = ph[16 * sg + 8], Pp = ph[16 * sg + 16];
                u32 ah4[4] = { P0, Pp, Pm, P0 };           // a3 == a0 (Toeplitz)
                u32 Qm = pl[16 * sg], Q0 = pl[16 * sg + 8], Qp = pl[16 * sg + 16];
                u32 al4[4] = { Q0, Qp, Qm, Q0 };
                #pragma unroll
                for (int kt = 0; kt < 4; kt++) {
                    const int md = sg + kt;                // 0..7
                    mma_bf16(acc[md], ah4, bfr[kt][0][0], bfr[kt][0][1]); // hi*hi
                    mma_bf16(acc[md], ah4, bfr[kt][1][0], bfr[kt][1][1]); // hi*lo
                    mma_bf16(acc[md], al4, bfr[kt][0][0], bfr[kt][0][1]); // lo*hi
                }
            }

            // ---- hoisted pair-table build for c+1 (warp-private) ----
            if (p == 1 && ci < 1)
                build_P(smem, tbase + (size_t)64 * 63, wid, lane);

            __syncthreads();   // staging writable (prev store readers done)

            // ---- stage this half's 8 m across all 128 d ----
            #pragma unroll
            for (int md = 0; md < 8; md++) {
                int d0 = 16 * md + gid;
                float* st = stgf + (2 * tig) * STG_MS + d0 * 9 + wid;
                st[0]            = acc[md][0];
                st[STG_MS]       = acc[md][1];
                st[72]           = acc[md][2];
                st[STG_MS + 72]  = acc[md][3];
            }
            __syncthreads();

            // ---- store (streamed) ----
            int m = 8 * p + wid;
            int a = (c - m) & 15;
            float* ob = out + ((size_t)(b * 256 + a * 16 + c) << 13)
                      + (size_t)(8 * qq) * 64 + lbase + l_off;
            const float* sm_m = stgf + wid * STG_MS + 72 * qq + l_off;
            #pragma unroll
            for (int jj = 0; jj < 32; jj++) {
                int dlo = jj & 7, dhi = jj >> 3;
                __stcs(ob + (size_t)(dlo + 32 * dhi) * 64,
                       sm_m[9 * dlo + 288 * dhi]);
            }
            // no trailing barrier: next mma half touches only warp-private
            // B/P reads; the next pre-stage barrier protects staging.
        }
    }
}

extern "C" void kernel_launch(void* const* d_in, const int* in_sizes, int n_in,
                              void* d_out, int out_size) {
    const float* s = (const float*)d_in[0];
    const float* t = (const float*)d_in[1];
    float* out = (float*)d_out;

    cudaFuncSetAttribute(conv_mma,
                         cudaFuncAttributeMaxDynamicSharedMemorySize, SMEM_TOTAL);

    dim3 grid(8, 32, 8);   // (l-oct, b, c-pair) = 2048 blocks, 2 c's each
    conv_mma<<<grid, 256, SMEM_TOTAL>>>(s, t, out);
}

// round 17
// speedup vs baseline: 1.4652x; 1.0041x over previous
#include <cuda_runtime.h>
#include <cuda_bf16.h>
#include <cstdint>

// out[b, a*16+c, d, l] = sum_k s[b,(c-a)%16,l,k] * t[b,c,l,d-k]  (linear conv)
// Per (b,c,l): D[128d x 16m] = A[128x64] * B[16x64]^T,
//   A[d][k] = t_pad[d-k] (Toeplitz), B[m][k] = s[b,m,l,k].
// mma.sync.m16n8k16 bf16, 3-term truncation split (hi*hi + hi*lo + lo*hi).
// R17 = R16 + double-buffered staging (barriers/c: 4 -> 2; pre-stage barrier
// provably redundant with two buffers) + XOR-swizzled 128B B rows to pay the
// smem bill. NO register cap (R15 lesson). 2 CTAs/SM, smem 112896B.

typedef unsigned int u32;

#define OFF_B    0
#define B_SIDE   2048          // 16 rows * 128B, chunk ^= (m&7) swizzle
#define B_PERL   4096          // x8 l = 32768
#define OFF_P    32768         // pair table: 8 l * 2 sides * 96 * 4B = 6144
#define OFF_STG  38912         // staging: 2 buffers x 36992B
#define STG_MS   1156          // staging m-stride (floats)
#define STG_BUF  9248          // buffer stride (floats) = 36992B
#define SMEM_TOTAL 112896
#define SRS      516           // s_raw m-stride (floats), 16B-aligned rows

__device__ __forceinline__ u32 pack_bf2(float lo, float hi) {   // {lo16, hi16}
    u32 r;
    asm("cvt.rn.satfinite.bf16x2.f32 %0, %1, %2;" : "=r"(r) : "f"(hi), "f"(lo));
    return r;
}
__device__ __forceinline__ void mma_bf16(float* c, const u32* a, u32 b0, u32 b1) {
    asm("mma.sync.aligned.m16n8k16.row.col.f32.bf16.bf16.f32 "
        "{%0,%1,%2,%3}, {%4,%5,%6,%7}, {%8,%9}, {%0,%1,%2,%3};"
        : "+f"(c[0]), "+f"(c[1]), "+f"(c[2]), "+f"(c[3])
        : "r"(a[0]), "r"(a[1]), "r"(a[2]), "r"(a[3]), "r"(b0), "r"(b1));
}

// warp-local pair-table build for l = w: P[e] = {t_pad[y], t_pad[y-1]}, y=e-14
__device__ __forceinline__ void build_P(char* smem, const float* __restrict__ tg,
                                        int w, int lane) {
    u32* ph = (u32*)(smem + OFF_P) + w * 192;
    #pragma unroll
    for (int j = 0; j < 3; j++) {
        int e = lane + 32 * j;              // 0..95
        int y = e - 14;
        float x0 = ((unsigned)y < 63u) ? __ldg(tg + y) : 0.0f;
        float x1 = ((unsigned)(y - 1) < 63u) ? __ldg(tg + y - 1) : 0.0f;
        u32 u0 = __float_as_uint(x0), u1 = __float_as_uint(x1);
        u32 hw = __byte_perm(u0, u1, 0x7632);          // {hi16(x0), hi16(x1)}
        float h0 = __uint_as_float(u0 & 0xFFFF0000u);
        float h1 = __uint_as_float(u1 & 0xFFFF0000u);
        ph[e]      = hw;
        ph[96 + e] = pack_bf2(x0 - h0, x1 - h1);
    }
}

__global__ __launch_bounds__(256, 2)
void conv_mma(const float* __restrict__ s_g,
              const float* __restrict__ t_g,
              float* __restrict__ out) {
    extern __shared__ char smem[];
    float* stgf = (float*)(smem + OFF_STG);
    const int tid = threadIdx.x, wid = tid >> 5, lane = tid & 31;
    const int gid = lane >> 2, tig = lane & 3;
    const int lq = blockIdx.x, b = blockIdx.y, cg = blockIdx.z;
    const int lbase = lq * 8;
    const float* tbase = t_g + (((size_t)b * 16 + cg * 2) * 64 + lbase + wid) * 63;

    // ---- prologue: stage s tile coalesced (overlays staging buffer 0) ----
    float* s_raw = stgf;                      // 16 m * 516 floats = 33024B
    {
        const float* sgb = s_g + ((size_t)b * 1024 + lbase) * 63;   // 16B-aligned
        for (int i = tid; i < 2016; i += 256) {                     // 16 m * 126 f4
            int m = i / 126, j = i - m * 126;
            float4 v = *(const float4*)(sgb + (size_t)m * 4032 + j * 4);
            *(float4*)(s_raw + m * SRS + j * 4) = v;
        }
    }
    __syncthreads();

    // ---- warp-local B build: warp w -> l = w; lane = (m, h); XOR swizzle ----
    {
        int m = lane >> 1, h = lane & 1;
        const float* sp = s_raw + m * SRS + wid * 63 + h * 32;
        u32 hw[16], lw[16];
        #pragma unroll
        for (int q = 0; q < 16; q++) {
            float x0 = sp[2 * q];                    // k = h*32+2q <= 62
            float x1 = 0.0f;
            if (h * 32 + 2 * q + 1 < 63) x1 = sp[2 * q + 1];
            u32 u0 = __float_as_uint(x0), u1 = __float_as_uint(x1);
            hw[q] = __byte_perm(u0, u1, 0x7632);
            float h0 = __uint_as_float(u0 & 0xFFFF0000u);
            float h1 = __uint_as_float(u1 & 0xFFFF0000u);
            lw[q] = pack_bf2(x0 - h0, x1 - h1);
        }
        char* bh = smem + OFF_B + wid * B_PERL + m * 128;
        char* bl = bh + B_SIDE;
        #pragma unroll
        for (int cc = 0; cc < 4; cc++) {
            int g = ((h * 4 + cc) ^ (m & 7)) * 16;   // swizzled chunk offset
            *(uint4*)(bh + g) =
                make_uint4(hw[cc*4], hw[cc*4+1], hw[cc*4+2], hw[cc*4+3]);
            *(uint4*)(bl + g) =
                make_uint4(lw[cc*4], lw[cc*4+1], lw[cc*4+2], lw[cc*4+3]);
        }
    }
    // pair table for first c (warp-private write/read: no barrier needed)
    build_P(smem, tbase, wid, lane);
    __syncthreads();   // B ready; s_raw consumed -> staging buffers free

    const int l_off = lane & 7, qq = lane >> 3;
    const char* bb = smem + OFF_B + wid * B_PERL;
    const u32* ph = (const u32*)(smem + OFF_P) + wid * 192 + (gid - 2 * tig + 6);
    const u32* pl = ph + 96;

    #pragma unroll 1
    for (int ci = 0; ci < 2; ci++) {
        const int c = cg * 2 + ci;

        #pragma unroll 1
        for (int p = 0; p < 2; p++) {          // p doubles as nt
            // ---- mainloop half: n-tile nt = p for this warp's l ----
            float acc[8][4];
            u32 bfr[4][2][2];   // [kt][side][b0/b1]
            #pragma unroll
            for (int kt = 0; kt < 4; kt++)
                #pragma unroll
                for (int sd = 0; sd < 2; sd++) {
                    const char* rw = bb + sd * B_SIDE + (8 * p + gid) * 128
                                   + tig * 4;
                    bfr[kt][sd][0] = *(const u32*)(rw + (((2*kt)   ^ gid) * 16));
                    bfr[kt][sd][1] = *(const u32*)(rw + (((2*kt+1) ^ gid) * 16));
                }
            #pragma unroll
            for (int md = 0; md < 8; md++)
                #pragma unroll
                for (int e = 0; e < 4; e++) acc[md][e] = 0.0f;

            #pragma unroll
            for (int sg = 0; sg < 5; sg++) {               // sigma = md - kt
                u32 Pm = ph[16 * sg], P0 = ph[16 * sg + 8], Pp = ph[16 * sg + 16];
                u32 ah4[4] = { P0, Pp, Pm, P0 };           // a3 == a0 (Toeplitz)
                u32 Qm = pl[16 * sg], Q0 = pl[16 * sg + 8], Qp = pl[16 * sg + 16];
                u32 al4[4] = { Q0, Qp, Qm, Q0 };
                #pragma unroll
                for (int kt = 0; kt < 4; kt++) {
                    const int md = sg + kt;                // 0..7
                    mma_bf16(acc[md], ah4, bfr[kt][0][0], bfr[kt][0][1]); // hi*hi
                    mma_bf16(acc[md], ah4, bfr[kt][1][0], bfr[kt][1][1]); // hi*lo
                    mma_bf16(acc[md], al4, bfr[kt][0][0], bfr[kt][0][1]); // lo*hi
                }
            }

            // ---- hoisted pair-table build for c+1 (warp-private) ----
            if (p == 1 && ci < 1)
                build_P(smem, tbase + (size_t)64 * 63, wid, lane);

            // ---- stage this half's 8 m into buffer p (no pre-barrier:
            //      double buffering makes the old "writable" barrier redundant)
            float* sbuf = stgf + p * STG_BUF;
            #pragma unroll
            for (int md = 0; md < 8; md++) {
                int d0 = 16 * md + gid;
                float* st = sbuf + (2 * tig) * STG_MS + d0 * 9 + wid;
                st[0]            = acc[md][0];
                st[STG_MS]       = acc[md][1];
                st[72]           = acc[md][2];
                st[STG_MS + 72]  = acc[md][3];
            }
            __syncthreads();

            // ---- store (streamed) ----
            int m = 8 * p + wid;
            int a = (c - m) & 15;
            float* ob = out + ((size_t)(b * 256 + a * 16 + c) << 13)
                      + (size_t)(8 * qq) * 64 + lbase + l_off;
            const float* sm_m = sbuf + wid * STG_MS + 72 * qq + l_off;
            #pragma unroll
            for (int jj = 0; jj < 32; jj++) {
                int dlo = jj & 7, dhi = jj >> 3;
                __stcs(ob + (size_t)(dlo + 32 * dhi) * 64,
                       sm_m[9 * dlo + 288 * dhi]);
            }
            // no trailing barrier: next phase stages into the OTHER buffer;
            // its post-stage barrier transitively orders this store's reads.
        }
    }
}

extern "C" void kernel_launch(void* const* d_in, const int* in_sizes, int n_in,
                              void* d_out, int out_size) {
    const float* s = (const float*)d_in[0];
    const float* t = (const float*)d_in[1];
    float* out = (float*)d_out;

    cudaFuncSetAttribute(conv_mma,
                         cudaFuncAttributeMaxDynamicSharedMemorySize, SMEM_TOTAL);

    dim3 grid(8, 32, 8);   // (l-oct, b, c-pair) = 2048 blocks, 2 c's each
    conv_mma<<<grid, 256, SMEM_TOTAL>>>(s, t, out);
}